// round 2
// baseline (speedup 1.0000x reference)
#include <cuda_runtime.h>
#include <math.h>

#define S_LEN   4096
#define HID     2304
#define NH      8
#define NKV     4
#define HD      256
#define QDIM    (NH * HD)    // 2048
#define KVDIM   (NKV * HD)   // 1024
#define SWIN    2048
#define SOFTCAPF 50.0f
#define ATTN_SCALE 0.0625f   // 256^-0.5

// Scratch (device globals; no runtime allocation allowed)
__device__ float g_q [S_LEN * QDIM];
__device__ float g_k [S_LEN * KVDIM];
__device__ float g_v [S_LEN * KVDIM];
__device__ float g_ao[S_LEN * QDIM];

// ---------------------------------------------------------------------------
// GEMM: C[M,N] = A[M,K] * B[N,K]^T   (torch Linear layout), all dims
// divisible by tile sizes (M%64==0, N%64==0, K%16==0 for this problem).
// ---------------------------------------------------------------------------
__global__ __launch_bounds__(256) void gemm_xwt(const float* __restrict__ A,
                                                const float* __restrict__ B,
                                                float* __restrict__ C,
                                                int M, int N, int K) {
    __shared__ float As[16][64];
    __shared__ float Bs[16][64];
    const int t  = threadIdx.x;
    const int tx = t & 15;        // 0..15 -> n micro
    const int ty = t >> 4;        // 0..15 -> m micro
    const int m0 = blockIdx.y * 64;
    const int n0 = blockIdx.x * 64;

    float acc[4][4];
#pragma unroll
    for (int i = 0; i < 4; i++)
#pragma unroll
        for (int j = 0; j < 4; j++) acc[i][j] = 0.f;

    const int lr = t >> 2;          // 0..63 : tile row
    const int lk = (t & 3) * 4;     // 0,4,8,12 : k offset

    for (int k0 = 0; k0 < K; k0 += 16) {
        float4 av = *(const float4*)&A[(size_t)(m0 + lr) * K + k0 + lk];
        float4 bv = *(const float4*)&B[(size_t)(n0 + lr) * K + k0 + lk];
        As[lk + 0][lr] = av.x; As[lk + 1][lr] = av.y;
        As[lk + 2][lr] = av.z; As[lk + 3][lr] = av.w;
        Bs[lk + 0][lr] = bv.x; Bs[lk + 1][lr] = bv.y;
        Bs[lk + 2][lr] = bv.z; Bs[lk + 3][lr] = bv.w;
        __syncthreads();
#pragma unroll
        for (int kk = 0; kk < 16; kk++) {
            float4 a = *(const float4*)&As[kk][ty * 4];
            float4 b = *(const float4*)&Bs[kk][tx * 4];
            acc[0][0] += a.x * b.x; acc[0][1] += a.x * b.y;
            acc[0][2] += a.x * b.z; acc[0][3] += a.x * b.w;
            acc[1][0] += a.y * b.x; acc[1][1] += a.y * b.y;
            acc[1][2] += a.y * b.z; acc[1][3] += a.y * b.w;
            acc[2][0] += a.z * b.x; acc[2][1] += a.z * b.y;
            acc[2][2] += a.z * b.z; acc[2][3] += a.z * b.w;
            acc[3][0] += a.w * b.x; acc[3][1] += a.w * b.y;
            acc[3][2] += a.w * b.z; acc[3][3] += a.w * b.w;
        }
        __syncthreads();
    }
#pragma unroll
    for (int i = 0; i < 4; i++) {
        float4 o = make_float4(acc[i][0], acc[i][1], acc[i][2], acc[i][3]);
        *(float4*)&C[(size_t)(m0 + ty * 4 + i) * N + n0 + tx * 4] = o;
    }
}

// ---------------------------------------------------------------------------
// RoPE (in-place on g_q / g_k). One block per position; angles in double
// (high-accuracy range reduction, ref is fp32 jax — noise is ~1e-4 level).
// ---------------------------------------------------------------------------
__global__ __launch_bounds__(256) void rope_kernel(const int* __restrict__ pos) {
    __shared__ float cs[128], sn[128];
    const int s = blockIdx.x;
    const double p = (double)pos[s];
    const int t = threadIdx.x;
    if (t < 128) {
        double invf = pow(10000.0, -2.0 * (double)t / 256.0);
        double ang = p * invf;
        cs[t] = (float)cos(ang);
        sn[t] = (float)sin(ang);
    }
    __syncthreads();
    // 12 heads total (8 q + 4 k), 128 rotation pairs each
    for (int idx = t; idx < (NH + NKV) * 128; idx += 256) {
        int h = idx >> 7;
        int d = idx & 127;
        float c = cs[d], ss = sn[d];
        float* base = (h < NH) ? (g_q + (size_t)s * QDIM + h * HD)
                               : (g_k + (size_t)s * KVDIM + (h - NH) * HD);
        float x1 = base[d];
        float x2 = base[d + 128];
        base[d]       = x1 * c - x2 * ss;
        base[d + 128] = x2 * c + x1 * ss;
    }
}

// ---------------------------------------------------------------------------
// Flash attention, fp32, sliding-window causal + softcap.
// Grid: (S/64, NH). Block: 256 threads.  BQ=64, BK=32.
// ---------------------------------------------------------------------------
#define BQ 64
#define BK 32
#define QP 257   // smem row pitch (odd -> conflict-free strided column reads)
#define SP 33    // score tile pitch

__global__ __launch_bounds__(256, 1) void attn_kernel(float* __restrict__ out) {
    extern __shared__ float sm[];
    float* Qs  = sm;                       // 64 * 257
    float* Ks  = Qs + 64 * QP;             // 32 * 257
    float* Vs  = Ks + 32 * QP;             // 32 * 257
    float* Ss  = Vs + 32 * QP;             // 64 * 33
    float* mbuf = Ss + 64 * SP;            // 64
    float* lbuf = mbuf + 64;               // 64
    float* abuf = lbuf + 64;               // 64

    const int t   = threadIdx.x;
    const int h   = blockIdx.y;
    const int q0  = blockIdx.x * BQ;
    const int hkv = h >> 1;                // GQA groups = 2

    // ---- load Q tile [64 x 256] ----
    for (int i = t; i < 64 * 64; i += 256) {
        int r = i >> 6, c = (i & 63) * 4;
        float4 qv = *(const float4*)&g_q[(size_t)(q0 + r) * QDIM + h * HD + c];
        float* dst = &Qs[r * QP + c];
        dst[0] = qv.x; dst[1] = qv.y; dst[2] = qv.z; dst[3] = qv.w;
    }
    if (t < 64) { mbuf[t] = -1e30f; lbuf[t] = 0.f; }

    // PV-phase mapping: 4 queries x 16 dims per thread
    const int tq = t & 15;        // qbase = 4*tq
    const int td = t >> 4;        // dbase = 16*td
    const int qb2 = 4 * tq;
    const int db  = 16 * td;
    // score-phase mapping: 4 queries x 2 keys per thread
    const int qb = 4 * (t >> 4);
    const int kb = 2 * (t & 15);

    float acc[4][16];
#pragma unroll
    for (int u = 0; u < 4; u++)
#pragma unroll
        for (int dd = 0; dd < 16; dd++) acc[u][dd] = 0.f;

    int jlo = q0 - (SWIN - 1);
    if (jlo < 0) jlo = 0;
    const int jstart = jlo & ~(BK - 1);
    const int jend   = q0 + BQ;

    for (int j0 = jstart; j0 < jend; j0 += BK) {
        __syncthreads();   // previous PV reads done before overwrite
        // ---- load K,V tiles [32 x 256] ----
        for (int i = t; i < 32 * 64; i += 256) {
            int r = i >> 6, c = (i & 63) * 4;
            size_t goff = (size_t)(j0 + r) * KVDIM + hkv * HD + c;
            float4 kv = *(const float4*)&g_k[goff];
            float4 vv = *(const float4*)&g_v[goff];
            float* kd = &Ks[r * QP + c];
            float* vd = &Vs[r * QP + c];
            kd[0] = kv.x; kd[1] = kv.y; kd[2] = kv.z; kd[3] = kv.w;
            vd[0] = vv.x; vd[1] = vv.y; vd[2] = vv.z; vd[3] = vv.w;
        }
        __syncthreads();

        // ---- scores: S[64x32] = Q * K^T ----
        float sc[4][2];
#pragma unroll
        for (int u = 0; u < 4; u++) { sc[u][0] = 0.f; sc[u][1] = 0.f; }
#pragma unroll 4
        for (int d = 0; d < 256; d++) {
            float k0v = Ks[kb * QP + d];
            float k1v = Ks[(kb + 1) * QP + d];
#pragma unroll
            for (int u = 0; u < 4; u++) {
                float qv = Qs[(qb + u) * QP + d];
                sc[u][0] += qv * k0v;
                sc[u][1] += qv * k1v;
            }
        }
#pragma unroll
        for (int u = 0; u < 4; u++) {
#pragma unroll
            for (int w = 0; w < 2; w++) {
                int qi = q0 + qb + u;
                int kj = j0 + kb + w;
                float sv = sc[u][w] * ATTN_SCALE;
                sv = SOFTCAPF * tanhf(sv * (1.0f / SOFTCAPF));
                bool valid = (kj <= qi) && ((qi - kj) < SWIN);
                Ss[(qb + u) * SP + kb + w] = valid ? sv : -1e30f;
            }
        }
        __syncthreads();

        // ---- online softmax update (one thread per query) ----
        if (t < 64) {
            float m = mbuf[t];
            float mold = m;
#pragma unroll 8
            for (int j = 0; j < BK; j++) m = fmaxf(m, Ss[t * SP + j]);
            float alpha = expf(mold - m);
            float lsum = 0.f;
#pragma unroll 8
            for (int j = 0; j < BK; j++) {
                float sv = Ss[t * SP + j];
                float pv = (sv > -1e29f) ? expf(sv - m) : 0.f;
                Ss[t * SP + j] = pv;
                lsum += pv;
            }
            mbuf[t] = m;
            lbuf[t] = lbuf[t] * alpha + lsum;
            abuf[t] = alpha;
        }
        __syncthreads();

        // ---- rescale + accumulate O += P * V ----
#pragma unroll
        for (int u = 0; u < 4; u++) {
            float a = abuf[qb2 + u];
#pragma unroll
            for (int dd = 0; dd < 16; dd++) acc[u][dd] *= a;
        }
        for (int j = 0; j < BK; j++) {
            float p0 = Ss[(qb2 + 0) * SP + j];
            float p1 = Ss[(qb2 + 1) * SP + j];
            float p2 = Ss[(qb2 + 2) * SP + j];
            float p3 = Ss[(qb2 + 3) * SP + j];
#pragma unroll
            for (int dd = 0; dd < 16; dd++) {
                float vv = Vs[j * QP + db + dd];
                acc[0][dd] += p0 * vv;
                acc[1][dd] += p1 * vv;
                acc[2][dd] += p2 * vv;
                acc[3][dd] += p3 * vv;
            }
        }
    }
    __syncthreads();

    // ---- normalize + write out [s][h*HD + d] ----
#pragma unroll
    for (int u = 0; u < 4; u++) {
        float inv_l = 1.0f / lbuf[qb2 + u];
        int qi = q0 + qb2 + u;
#pragma unroll
        for (int dd = 0; dd < 16; dd++) {
            out[(size_t)qi * QDIM + h * HD + db + dd] = acc[u][dd] * inv_l;
        }
    }
}

// ---------------------------------------------------------------------------
// Launch
// ---------------------------------------------------------------------------
extern "C" void kernel_launch(void* const* d_in, const int* in_sizes, int n_in,
                              void* d_out, int out_size) {
    const float* x   = (const float*)d_in[0];   // [1,4096,2304]
    const int*   pos = (const int*)  d_in[1];   // [1,4096]
    const float* Wq  = (const float*)d_in[2];   // [2048,2304]
    const float* Wk  = (const float*)d_in[3];   // [1024,2304]
    const float* Wv  = (const float*)d_in[4];   // [1024,2304]
    const float* Wo  = (const float*)d_in[5];   // [2304,2048]
    float* out = (float*)d_out;                 // [1,4096,2304]

    float *q, *k, *v, *ao;
    cudaGetSymbolAddress((void**)&q,  g_q);
    cudaGetSymbolAddress((void**)&k,  g_k);
    cudaGetSymbolAddress((void**)&v,  g_v);
    cudaGetSymbolAddress((void**)&ao, g_ao);

    // QKV projections
    gemm_xwt<<<dim3(QDIM / 64,  S_LEN / 64), 256>>>(x, Wq, q, S_LEN, QDIM,  HID);
    gemm_xwt<<<dim3(KVDIM / 64, S_LEN / 64), 256>>>(x, Wk, k, S_LEN, KVDIM, HID);
    gemm_xwt<<<dim3(KVDIM / 64, S_LEN / 64), 256>>>(x, Wv, v, S_LEN, KVDIM, HID);

    // RoPE in place
    rope_kernel<<<S_LEN, 256>>>(pos);

    // Flash attention
    size_t smem = (size_t)(64 * QP + 32 * QP + 32 * QP + 64 * SP + 3 * 64) * sizeof(float);
    cudaFuncSetAttribute(attn_kernel, cudaFuncAttributeMaxDynamicSharedMemorySize, (int)smem);
    attn_kernel<<<dim3(S_LEN / BQ, NH), 256, smem>>>(ao);

    // Output projection
    gemm_xwt<<<dim3(HID / 64, S_LEN / 64), 256>>>(ao, Wo, out, S_LEN, HID, QDIM);
}

// round 4
// speedup vs baseline: 3.5891x; 3.5891x over previous
#include <cuda_runtime.h>
#include <math.h>

#define S_LEN   4096
#define HID     2304
#define NH      8
#define NKV     4
#define HD      256
#define QDIM    (NH * HD)    // 2048
#define KVDIM   (NKV * HD)   // 1024
#define SWIN    2048
#define SOFTCAPF 50.0f
#define ATTN_SCALE 0.0625f   // 256^-0.5

// Scratch (device globals; no runtime allocation allowed)
__device__ float g_q [S_LEN * QDIM];
__device__ float g_k [S_LEN * KVDIM];
__device__ float g_v [S_LEN * KVDIM];
__device__ float g_ao[S_LEN * QDIM];

__device__ __forceinline__ unsigned f2tf(float f) {
    unsigned u;
    asm("cvt.rna.tf32.f32 %0, %1;" : "=r"(u) : "f"(f));
    return u;
}

__device__ __forceinline__ void mma_tf32(float& c0, float& c1, float& c2, float& c3,
                                         unsigned a0, unsigned a1, unsigned a2, unsigned a3,
                                         unsigned b0, unsigned b1) {
    asm volatile(
        "mma.sync.aligned.m16n8k8.row.col.f32.tf32.tf32.f32 "
        "{%0,%1,%2,%3},{%4,%5,%6,%7},{%8,%9},{%0,%1,%2,%3};\n"
        : "+f"(c0), "+f"(c1), "+f"(c2), "+f"(c3)
        : "r"(a0), "r"(a1), "r"(a2), "r"(a3), "r"(b0), "r"(b1));
}

// ---------------------------------------------------------------------------
// GEMM: C[M,N] = A[M,K] * B[N,K]^T  via tf32 mma.sync m16n8k8.
// CTA tile 128x64, 4 warps (2x2), warp tile 64x32. K chunk 32.
// Requires M%128==0, N%64==0, K%32==0 (true for all 4 GEMMs here).
// ---------------------------------------------------------------------------
#define GP 36   // smem k-pitch (32 + 4): frag-read banks = 4g + tig (conflict-free)

__global__ __launch_bounds__(128) void gemm_tf32(const float* __restrict__ A,
                                                 const float* __restrict__ B,
                                                 float* __restrict__ C,
                                                 int M, int N, int K) {
    __shared__ unsigned As[128 * GP];
    __shared__ unsigned Bs[64 * GP];
    const int t    = threadIdx.x;
    const int lane = t & 31;
    const int wid  = t >> 5;
    const int g    = lane >> 2;
    const int tig  = lane & 3;
    const int wm   = (wid >> 1) * 64;   // warp m offset in tile
    const int wn   = (wid & 1) * 32;    // warp n offset in tile
    const int m0   = blockIdx.y * 128;
    const int n0   = blockIdx.x * 64;

    float acc[4][4][4];   // [mtile16][ntile8][frag]
#pragma unroll
    for (int mt = 0; mt < 4; mt++)
#pragma unroll
        for (int nt = 0; nt < 4; nt++)
#pragma unroll
            for (int c = 0; c < 4; c++) acc[mt][nt][c] = 0.f;

    for (int k0 = 0; k0 < K; k0 += 32) {
        // load A tile 128x32
#pragma unroll
        for (int i = 0; i < 8; i++) {
            int idx = t + 128 * i;
            int r = idx >> 3, kc = (idx & 7) * 4;
            float4 v = *(const float4*)&A[(size_t)(m0 + r) * K + k0 + kc];
            uint4 u = make_uint4(f2tf(v.x), f2tf(v.y), f2tf(v.z), f2tf(v.w));
            *(uint4*)&As[r * GP + kc] = u;
        }
        // load B tile 64x32
#pragma unroll
        for (int i = 0; i < 4; i++) {
            int idx = t + 128 * i;
            int r = idx >> 3, kc = (idx & 7) * 4;
            float4 v = *(const float4*)&B[(size_t)(n0 + r) * K + k0 + kc];
            uint4 u = make_uint4(f2tf(v.x), f2tf(v.y), f2tf(v.z), f2tf(v.w));
            *(uint4*)&Bs[r * GP + kc] = u;
        }
        __syncthreads();

#pragma unroll
        for (int ks = 0; ks < 32; ks += 8) {
            unsigned a[4][4];
#pragma unroll
            for (int mt = 0; mt < 4; mt++) {
                int mr = wm + mt * 16;
                a[mt][0] = As[(mr + g) * GP + ks + tig];
                a[mt][1] = As[(mr + g + 8) * GP + ks + tig];
                a[mt][2] = As[(mr + g) * GP + ks + tig + 4];
                a[mt][3] = As[(mr + g + 8) * GP + ks + tig + 4];
            }
#pragma unroll
            for (int nt = 0; nt < 4; nt++) {
                unsigned b0 = Bs[(wn + nt * 8 + g) * GP + ks + tig];
                unsigned b1 = Bs[(wn + nt * 8 + g) * GP + ks + tig + 4];
#pragma unroll
                for (int mt = 0; mt < 4; mt++)
                    mma_tf32(acc[mt][nt][0], acc[mt][nt][1], acc[mt][nt][2], acc[mt][nt][3],
                             a[mt][0], a[mt][1], a[mt][2], a[mt][3], b0, b1);
            }
        }
        __syncthreads();
    }

#pragma unroll
    for (int mt = 0; mt < 4; mt++) {
        int row = m0 + wm + mt * 16 + g;
#pragma unroll
        for (int nt = 0; nt < 4; nt++) {
            int col = n0 + wn + nt * 8 + 2 * tig;
            *(float2*)&C[(size_t)row * N + col]       = make_float2(acc[mt][nt][0], acc[mt][nt][1]);
            *(float2*)&C[(size_t)(row + 8) * N + col] = make_float2(acc[mt][nt][2], acc[mt][nt][3]);
        }
    }
}

// ---------------------------------------------------------------------------
// RoPE (in-place on g_q / g_k), unchanged from round 1.
// ---------------------------------------------------------------------------
__global__ __launch_bounds__(256) void rope_kernel(const int* __restrict__ pos) {
    __shared__ float cs[128], sn[128];
    const int s = blockIdx.x;
    const double p = (double)pos[s];
    const int t = threadIdx.x;
    if (t < 128) {
        double invf = pow(10000.0, -2.0 * (double)t / 256.0);
        double ang = p * invf;
        cs[t] = (float)cos(ang);
        sn[t] = (float)sin(ang);
    }
    __syncthreads();
    for (int idx = t; idx < (NH + NKV) * 128; idx += 256) {
        int h = idx >> 7;
        int d = idx & 127;
        float c = cs[d], ss = sn[d];
        float* base = (h < NH) ? (g_q + (size_t)s * QDIM + h * HD)
                               : (g_k + (size_t)s * KVDIM + (h - NH) * HD);
        float x1 = base[d];
        float x2 = base[d + 128];
        base[d]       = x1 * c - x2 * ss;
        base[d + 128] = x2 * c + x1 * ss;
    }
}

// ---------------------------------------------------------------------------
// Flash attention via tf32 mma. BQ=64, BK=32, 4 warps; each warp owns 16
// query rows end-to-end (O accumulator fully in registers).
// Qs pitch 260: frag banks 4g+tig conflict-free.
// Ks pitch 260: b-frag banks 4g+tig conflict-free.
// Vs pitch 264 (untransposed): PV b-frag banks 8*tig+g conflict-free.
// ---------------------------------------------------------------------------
#define BQ 64
#define BK 32
#define QPITCH 260
#define KPITCH 260
#define VPITCH 264

__global__ __launch_bounds__(128, 1) void attn_tf32(float* __restrict__ out) {
    extern __shared__ unsigned sm[];
    unsigned* Qs = sm;                        // [64][260]
    unsigned* Ks = Qs + 64 * QPITCH;          // [32][260]
    unsigned* Vs = Ks + 32 * KPITCH;          // [32][264]

    const int t    = threadIdx.x;
    const int lane = t & 31;
    const int wid  = t >> 5;
    const int g    = lane >> 2;
    const int tig  = lane & 3;
    const int h    = blockIdx.y;
    const int q0   = blockIdx.x * BQ;
    const int hkv  = h >> 1;
    const int rbase = wid * 16;
    const int qi_lo = q0 + rbase + g;
    const int qi_hi = qi_lo + 8;

    // ---- load Q tile [64 x 256] -> tf32 smem ----
    for (int i = t; i < 64 * 64; i += 128) {
        int r = i >> 6, c = (i & 63) * 4;
        float4 v = *(const float4*)&g_q[(size_t)(q0 + r) * QDIM + h * HD + c];
        uint4 u = make_uint4(f2tf(v.x), f2tf(v.y), f2tf(v.z), f2tf(v.w));
        *(uint4*)&Qs[r * QPITCH + c] = u;
    }

    float o[32][4];   // O accumulator: 32 n-tiles of 8 over HD=256
#pragma unroll
    for (int nt = 0; nt < 32; nt++)
#pragma unroll
        for (int c = 0; c < 4; c++) o[nt][c] = 0.f;

    float m_lo = -1e30f, m_hi = -1e30f, l_lo = 0.f, l_hi = 0.f;

    int jlo = q0 - (SWIN - 1);
    if (jlo < 0) jlo = 0;
    const int jstart = jlo & ~(BK - 1);
    const int jend   = q0 + BQ;

    for (int j0 = jstart; j0 < jend; j0 += BK) {
        __syncthreads();   // prior-tile reads done before overwrite
        // ---- load K, V tiles [32 x 256] ----
        for (int i = t; i < 32 * 64; i += 128) {
            int r = i >> 6, c = (i & 63) * 4;
            size_t off = (size_t)(j0 + r) * KVDIM + hkv * HD + c;
            float4 kv = *(const float4*)&g_k[off];
            float4 vv = *(const float4*)&g_v[off];
            uint4 ku = make_uint4(f2tf(kv.x), f2tf(kv.y), f2tf(kv.z), f2tf(kv.w));
            uint4 vu = make_uint4(f2tf(vv.x), f2tf(vv.y), f2tf(vv.z), f2tf(vv.w));
            *(uint4*)&Ks[r * KPITCH + c] = ku;
            *(uint4*)&Vs[r * VPITCH + c] = vu;
        }
        __syncthreads();

        // ---- QK^T scores: warp's 16 rows x 32 keys ----
        float sc[4][4];
#pragma unroll
        for (int nt = 0; nt < 4; nt++)
#pragma unroll
            for (int c = 0; c < 4; c++) sc[nt][c] = 0.f;

#pragma unroll 8
        for (int ks = 0; ks < 256; ks += 8) {
            unsigned a0 = Qs[(rbase + g) * QPITCH + ks + tig];
            unsigned a1 = Qs[(rbase + g + 8) * QPITCH + ks + tig];
            unsigned a2 = Qs[(rbase + g) * QPITCH + ks + tig + 4];
            unsigned a3 = Qs[(rbase + g + 8) * QPITCH + ks + tig + 4];
#pragma unroll
            for (int nt = 0; nt < 4; nt++) {
                unsigned b0 = Ks[(nt * 8 + g) * KPITCH + ks + tig];
                unsigned b1 = Ks[(nt * 8 + g) * KPITCH + ks + tig + 4];
                mma_tf32(sc[nt][0], sc[nt][1], sc[nt][2], sc[nt][3],
                         a0, a1, a2, a3, b0, b1);
            }
        }

        // ---- softcap + mask, thread-local max ----
        float tmax_lo = -1e30f, tmax_hi = -1e30f;
#pragma unroll
        for (int nt = 0; nt < 4; nt++) {
#pragma unroll
            for (int c = 0; c < 4; c++) {
                int j  = j0 + nt * 8 + 2 * tig + (c & 1);
                int qi = (c < 2) ? qi_lo : qi_hi;
                float s = sc[nt][c] * ATTN_SCALE;
                s = SOFTCAPF * tanhf(s * (1.0f / SOFTCAPF));
                bool valid = (j <= qi) && ((qi - j) < SWIN);
                s = valid ? s : -1e30f;
                sc[nt][c] = s;
                if (c < 2) tmax_lo = fmaxf(tmax_lo, s);
                else       tmax_hi = fmaxf(tmax_hi, s);
            }
        }
        // quad reduce max (lanes of a quad share the same rows)
        tmax_lo = fmaxf(tmax_lo, __shfl_xor_sync(0xffffffffu, tmax_lo, 1));
        tmax_lo = fmaxf(tmax_lo, __shfl_xor_sync(0xffffffffu, tmax_lo, 2));
        tmax_hi = fmaxf(tmax_hi, __shfl_xor_sync(0xffffffffu, tmax_hi, 1));
        tmax_hi = fmaxf(tmax_hi, __shfl_xor_sync(0xffffffffu, tmax_hi, 2));

        float mnew_lo = fmaxf(m_lo, tmax_lo);
        float mnew_hi = fmaxf(m_hi, tmax_hi);
        float al = __expf(m_lo - mnew_lo);
        float ah = __expf(m_hi - mnew_hi);
        m_lo = mnew_lo; m_hi = mnew_hi;

        // ---- p = exp(s - m), partial row sums ----
        float ps_lo = 0.f, ps_hi = 0.f;
#pragma unroll
        for (int nt = 0; nt < 4; nt++) {
#pragma unroll
            for (int c = 0; c < 4; c++) {
                float s = sc[nt][c];
                float mm = (c < 2) ? m_lo : m_hi;
                float pv = (s > -1e29f) ? __expf(s - mm) : 0.f;
                sc[nt][c] = pv;
                if (c < 2) ps_lo += pv; else ps_hi += pv;
            }
        }
        l_lo = l_lo * al + ps_lo;
        l_hi = l_hi * ah + ps_hi;

        // ---- rescale O ----
#pragma unroll
        for (int nt = 0; nt < 32; nt++) {
            o[nt][0] *= al; o[nt][1] *= al;
            o[nt][2] *= ah; o[nt][3] *= ah;
        }

        // ---- PV: O += P * V ----
        const int src0 = (lane & ~3) | (tig >> 1);
        const int src1 = src0 + 2;
#pragma unroll
        for (int kk = 0; kk < 4; kk++) {
            // permute C-fragment p (cols 2tig,2tig+1) into A-fragment (cols tig, tig+4)
            float s0 = __shfl_sync(0xffffffffu, sc[kk][0], src0);
            float s1 = __shfl_sync(0xffffffffu, sc[kk][1], src0);
            float s2 = __shfl_sync(0xffffffffu, sc[kk][2], src0);
            float s3 = __shfl_sync(0xffffffffu, sc[kk][3], src0);
            float u0 = __shfl_sync(0xffffffffu, sc[kk][0], src1);
            float u1 = __shfl_sync(0xffffffffu, sc[kk][1], src1);
            float u2 = __shfl_sync(0xffffffffu, sc[kk][2], src1);
            float u3 = __shfl_sync(0xffffffffu, sc[kk][3], src1);
            unsigned a0 = f2tf((tig & 1) ? s1 : s0);   // row lo, k = kk*8+tig
            unsigned a1 = f2tf((tig & 1) ? s3 : s2);   // row hi, k = kk*8+tig
            unsigned a2 = f2tf((tig & 1) ? u1 : u0);   // row lo, k = kk*8+tig+4
            unsigned a3 = f2tf((tig & 1) ? u3 : u2);   // row hi, k = kk*8+tig+4
#pragma unroll
            for (int nt = 0; nt < 32; nt++) {
                unsigned b0 = Vs[(kk * 8 + tig) * VPITCH + nt * 8 + g];
                unsigned b1 = Vs[(kk * 8 + tig + 4) * VPITCH + nt * 8 + g];
                mma_tf32(o[nt][0], o[nt][1], o[nt][2], o[nt][3],
                         a0, a1, a2, a3, b0, b1);
            }
        }
    }

    // ---- final row-sum reduce + normalize + write ----
    l_lo += __shfl_xor_sync(0xffffffffu, l_lo, 1);
    l_lo += __shfl_xor_sync(0xffffffffu, l_lo, 2);
    l_hi += __shfl_xor_sync(0xffffffffu, l_hi, 1);
    l_hi += __shfl_xor_sync(0xffffffffu, l_hi, 2);
    float inv_lo = 1.0f / l_lo;
    float inv_hi = 1.0f / l_hi;

#pragma unroll
    for (int nt = 0; nt < 32; nt++) {
        int col = h * HD + nt * 8 + 2 * tig;
        *(float2*)&out[(size_t)qi_lo * QDIM + col] = make_float2(o[nt][0] * inv_lo, o[nt][1] * inv_lo);
        *(float2*)&out[(size_t)qi_hi * QDIM + col] = make_float2(o[nt][2] * inv_hi, o[nt][3] * inv_hi);
    }
}

// ---------------------------------------------------------------------------
// Launch
// ---------------------------------------------------------------------------
extern "C" void kernel_launch(void* const* d_in, const int* in_sizes, int n_in,
                              void* d_out, int out_size) {
    const float* x   = (const float*)d_in[0];
    const int*   pos = (const int*)  d_in[1];
    const float* Wq  = (const float*)d_in[2];
    const float* Wk  = (const float*)d_in[3];
    const float* Wv  = (const float*)d_in[4];
    const float* Wo  = (const float*)d_in[5];
    float* out = (float*)d_out;

    float *q, *k, *v, *ao;
    cudaGetSymbolAddress((void**)&q,  g_q);
    cudaGetSymbolAddress((void**)&k,  g_k);
    cudaGetSymbolAddress((void**)&v,  g_v);
    cudaGetSymbolAddress((void**)&ao, g_ao);

    // QKV projections (tf32 tensor-core GEMMs)
    gemm_tf32<<<dim3(QDIM / 64,  S_LEN / 128), 128>>>(x, Wq, q, S_LEN, QDIM,  HID);
    gemm_tf32<<<dim3(KVDIM / 64, S_LEN / 128), 128>>>(x, Wk, k, S_LEN, KVDIM, HID);
    gemm_tf32<<<dim3(KVDIM / 64, S_LEN / 128), 128>>>(x, Wv, v, S_LEN, KVDIM, HID);

    // RoPE in place
    rope_kernel<<<S_LEN, 256>>>(pos);

    // Flash attention (tf32 tensor-core)
    size_t smem = (size_t)(64 * QPITCH + 32 * KPITCH + 32 * VPITCH) * sizeof(unsigned);
    cudaFuncSetAttribute(attn_tf32, cudaFuncAttributeMaxDynamicSharedMemorySize, (int)smem);
    attn_tf32<<<dim3(S_LEN / BQ, NH), 128, smem>>>(ao);

    // Output projection
    gemm_tf32<<<dim3(HID / 64, S_LEN / 128), 128>>>(ao, Wo, out, S_LEN, HID, QDIM);
}

// round 5
// speedup vs baseline: 3.6072x; 1.0050x over previous
#include <cuda_runtime.h>
#include <math.h>

#define S_LEN   4096
#define HID     2304
#define NH      8
#define NKV     4
#define HD      256
#define QDIM    (NH * HD)    // 2048
#define KVDIM   (NKV * HD)   // 1024
#define SWIN    2048
#define SOFTCAPF 50.0f
#define ATTN_SCALE 0.0625f   // 256^-0.5

// Scratch (device globals; no runtime allocation allowed)
__device__ float g_q [S_LEN * QDIM];
__device__ float g_k [S_LEN * KVDIM];
__device__ float g_v [S_LEN * KVDIM];
__device__ float g_ao[S_LEN * QDIM];

__device__ __forceinline__ unsigned f2tf(float f) {
    unsigned u;
    asm("cvt.rna.tf32.f32 %0, %1;" : "=r"(u) : "f"(f));
    return u;
}

__device__ __forceinline__ void mma_tf32(float& c0, float& c1, float& c2, float& c3,
                                         unsigned a0, unsigned a1, unsigned a2, unsigned a3,
                                         unsigned b0, unsigned b1) {
    asm volatile(
        "mma.sync.aligned.m16n8k8.row.col.f32.tf32.tf32.f32 "
        "{%0,%1,%2,%3},{%4,%5,%6,%7},{%8,%9},{%0,%1,%2,%3};\n"
        : "+f"(c0), "+f"(c1), "+f"(c2), "+f"(c3)
        : "r"(a0), "r"(a1), "r"(a2), "r"(a3), "r"(b0), "r"(b1));
}

// ---------------------------------------------------------------------------
// GEMM: C[M,N] = A[M,K] * B[N,K]^T  via tf32 mma.sync m16n8k8.
// CTA tile 128x64, 4 warps (2x2), warp tile 64x32. K chunk 32.
// Requires M%128==0, N%64==0, K%32==0 (true for all 4 GEMMs here).
// ---------------------------------------------------------------------------
#define GP 36   // smem k-pitch (32 + 4): frag-read banks = 4g + tig (conflict-free)

__global__ __launch_bounds__(128) void gemm_tf32(const float* __restrict__ A,
                                                 const float* __restrict__ B,
                                                 float* __restrict__ C,
                                                 int M, int N, int K) {
    __shared__ unsigned As[128 * GP];
    __shared__ unsigned Bs[64 * GP];
    const int t    = threadIdx.x;
    const int lane = t & 31;
    const int wid  = t >> 5;
    const int g    = lane >> 2;
    const int tig  = lane & 3;
    const int wm   = (wid >> 1) * 64;   // warp m offset in tile
    const int wn   = (wid & 1) * 32;    // warp n offset in tile
    const int m0   = blockIdx.y * 128;
    const int n0   = blockIdx.x * 64;

    float acc[4][4][4];   // [mtile16][ntile8][frag]
#pragma unroll
    for (int mt = 0; mt < 4; mt++)
#pragma unroll
        for (int nt = 0; nt < 4; nt++)
#pragma unroll
            for (int c = 0; c < 4; c++) acc[mt][nt][c] = 0.f;

    for (int k0 = 0; k0 < K; k0 += 32) {
        // load A tile 128x32
#pragma unroll
        for (int i = 0; i < 8; i++) {
            int idx = t + 128 * i;
            int r = idx >> 3, kc = (idx & 7) * 4;
            float4 v = *(const float4*)&A[(size_t)(m0 + r) * K + k0 + kc];
            uint4 u = make_uint4(f2tf(v.x), f2tf(v.y), f2tf(v.z), f2tf(v.w));
            *(uint4*)&As[r * GP + kc] = u;
        }
        // load B tile 64x32
#pragma unroll
        for (int i = 0; i < 4; i++) {
            int idx = t + 128 * i;
            int r = idx >> 3, kc = (idx & 7) * 4;
            float4 v = *(const float4*)&B[(size_t)(n0 + r) * K + k0 + kc];
            uint4 u = make_uint4(f2tf(v.x), f2tf(v.y), f2tf(v.z), f2tf(v.w));
            *(uint4*)&Bs[r * GP + kc] = u;
        }
        __syncthreads();

#pragma unroll
        for (int ks = 0; ks < 32; ks += 8) {
            unsigned a[4][4];
#pragma unroll
            for (int mt = 0; mt < 4; mt++) {
                int mr = wm + mt * 16;
                a[mt][0] = As[(mr + g) * GP + ks + tig];
                a[mt][1] = As[(mr + g + 8) * GP + ks + tig];
                a[mt][2] = As[(mr + g) * GP + ks + tig + 4];
                a[mt][3] = As[(mr + g + 8) * GP + ks + tig + 4];
            }
#pragma unroll
            for (int nt = 0; nt < 4; nt++) {
                unsigned b0 = Bs[(wn + nt * 8 + g) * GP + ks + tig];
                unsigned b1 = Bs[(wn + nt * 8 + g) * GP + ks + tig + 4];
#pragma unroll
                for (int mt = 0; mt < 4; mt++)
                    mma_tf32(acc[mt][nt][0], acc[mt][nt][1], acc[mt][nt][2], acc[mt][nt][3],
                             a[mt][0], a[mt][1], a[mt][2], a[mt][3], b0, b1);
            }
        }
        __syncthreads();
    }

#pragma unroll
    for (int mt = 0; mt < 4; mt++) {
        int row = m0 + wm + mt * 16 + g;
#pragma unroll
        for (int nt = 0; nt < 4; nt++) {
            int col = n0 + wn + nt * 8 + 2 * tig;
            *(float2*)&C[(size_t)row * N + col]       = make_float2(acc[mt][nt][0], acc[mt][nt][1]);
            *(float2*)&C[(size_t)(row + 8) * N + col] = make_float2(acc[mt][nt][2], acc[mt][nt][3]);
        }
    }
}

// ---------------------------------------------------------------------------
// RoPE (in-place on g_q / g_k), unchanged from round 1.
// ---------------------------------------------------------------------------
__global__ __launch_bounds__(256) void rope_kernel(const int* __restrict__ pos) {
    __shared__ float cs[128], sn[128];
    const int s = blockIdx.x;
    const double p = (double)pos[s];
    const int t = threadIdx.x;
    if (t < 128) {
        double invf = pow(10000.0, -2.0 * (double)t / 256.0);
        double ang = p * invf;
        cs[t] = (float)cos(ang);
        sn[t] = (float)sin(ang);
    }
    __syncthreads();
    for (int idx = t; idx < (NH + NKV) * 128; idx += 256) {
        int h = idx >> 7;
        int d = idx & 127;
        float c = cs[d], ss = sn[d];
        float* base = (h < NH) ? (g_q + (size_t)s * QDIM + h * HD)
                               : (g_k + (size_t)s * KVDIM + (h - NH) * HD);
        float x1 = base[d];
        float x2 = base[d + 128];
        base[d]       = x1 * c - x2 * ss;
        base[d + 128] = x2 * c + x1 * ss;
    }
}

// ---------------------------------------------------------------------------
// Flash attention via tf32 mma. BQ=64, BK=32, 4 warps; each warp owns 16
// query rows end-to-end (O accumulator fully in registers).
// Qs pitch 260: frag banks 4g+tig conflict-free.
// Ks pitch 260: b-frag banks 4g+tig conflict-free.
// Vs pitch 264 (untransposed): PV b-frag banks 8*tig+g conflict-free.
// ---------------------------------------------------------------------------
#define BQ 64
#define BK 32
#define QPITCH 260
#define KPITCH 260
#define VPITCH 264

__global__ __launch_bounds__(128, 1) void attn_tf32(float* __restrict__ out) {
    extern __shared__ unsigned sm[];
    unsigned* Qs = sm;                        // [64][260]
    unsigned* Ks = Qs + 64 * QPITCH;          // [32][260]
    unsigned* Vs = Ks + 32 * KPITCH;          // [32][264]

    const int t    = threadIdx.x;
    const int lane = t & 31;
    const int wid  = t >> 5;
    const int g    = lane >> 2;
    const int tig  = lane & 3;
    const int h    = blockIdx.y;
    const int q0   = blockIdx.x * BQ;
    const int hkv  = h >> 1;
    const int rbase = wid * 16;
    const int qi_lo = q0 + rbase + g;
    const int qi_hi = qi_lo + 8;

    // ---- load Q tile [64 x 256] -> tf32 smem ----
    for (int i = t; i < 64 * 64; i += 128) {
        int r = i >> 6, c = (i & 63) * 4;
        float4 v = *(const float4*)&g_q[(size_t)(q0 + r) * QDIM + h * HD + c];
        uint4 u = make_uint4(f2tf(v.x), f2tf(v.y), f2tf(v.z), f2tf(v.w));
        *(uint4*)&Qs[r * QPITCH + c] = u;
    }

    float o[32][4];   // O accumulator: 32 n-tiles of 8 over HD=256
#pragma unroll
    for (int nt = 0; nt < 32; nt++)
#pragma unroll
        for (int c = 0; c < 4; c++) o[nt][c] = 0.f;

    float m_lo = -1e30f, m_hi = -1e30f, l_lo = 0.f, l_hi = 0.f;

    int jlo = q0 - (SWIN - 1);
    if (jlo < 0) jlo = 0;
    const int jstart = jlo & ~(BK - 1);
    const int jend   = q0 + BQ;

    for (int j0 = jstart; j0 < jend; j0 += BK) {
        __syncthreads();   // prior-tile reads done before overwrite
        // ---- load K, V tiles [32 x 256] ----
        for (int i = t; i < 32 * 64; i += 128) {
            int r = i >> 6, c = (i & 63) * 4;
            size_t off = (size_t)(j0 + r) * KVDIM + hkv * HD + c;
            float4 kv = *(const float4*)&g_k[off];
            float4 vv = *(const float4*)&g_v[off];
            uint4 ku = make_uint4(f2tf(kv.x), f2tf(kv.y), f2tf(kv.z), f2tf(kv.w));
            uint4 vu = make_uint4(f2tf(vv.x), f2tf(vv.y), f2tf(vv.z), f2tf(vv.w));
            *(uint4*)&Ks[r * KPITCH + c] = ku;
            *(uint4*)&Vs[r * VPITCH + c] = vu;
        }
        __syncthreads();

        // ---- QK^T scores: warp's 16 rows x 32 keys ----
        float sc[4][4];
#pragma unroll
        for (int nt = 0; nt < 4; nt++)
#pragma unroll
            for (int c = 0; c < 4; c++) sc[nt][c] = 0.f;

#pragma unroll 8
        for (int ks = 0; ks < 256; ks += 8) {
            unsigned a0 = Qs[(rbase + g) * QPITCH + ks + tig];
            unsigned a1 = Qs[(rbase + g + 8) * QPITCH + ks + tig];
            unsigned a2 = Qs[(rbase + g) * QPITCH + ks + tig + 4];
            unsigned a3 = Qs[(rbase + g + 8) * QPITCH + ks + tig + 4];
#pragma unroll
            for (int nt = 0; nt < 4; nt++) {
                unsigned b0 = Ks[(nt * 8 + g) * KPITCH + ks + tig];
                unsigned b1 = Ks[(nt * 8 + g) * KPITCH + ks + tig + 4];
                mma_tf32(sc[nt][0], sc[nt][1], sc[nt][2], sc[nt][3],
                         a0, a1, a2, a3, b0, b1);
            }
        }

        // ---- softcap + mask, thread-local max ----
        float tmax_lo = -1e30f, tmax_hi = -1e30f;
#pragma unroll
        for (int nt = 0; nt < 4; nt++) {
#pragma unroll
            for (int c = 0; c < 4; c++) {
                int j  = j0 + nt * 8 + 2 * tig + (c & 1);
                int qi = (c < 2) ? qi_lo : qi_hi;
                float s = sc[nt][c] * ATTN_SCALE;
                s = SOFTCAPF * tanhf(s * (1.0f / SOFTCAPF));
                bool valid = (j <= qi) && ((qi - j) < SWIN);
                s = valid ? s : -1e30f;
                sc[nt][c] = s;
                if (c < 2) tmax_lo = fmaxf(tmax_lo, s);
                else       tmax_hi = fmaxf(tmax_hi, s);
            }
        }
        // quad reduce max (lanes of a quad share the same rows)
        tmax_lo = fmaxf(tmax_lo, __shfl_xor_sync(0xffffffffu, tmax_lo, 1));
        tmax_lo = fmaxf(tmax_lo, __shfl_xor_sync(0xffffffffu, tmax_lo, 2));
        tmax_hi = fmaxf(tmax_hi, __shfl_xor_sync(0xffffffffu, tmax_hi, 1));
        tmax_hi = fmaxf(tmax_hi, __shfl_xor_sync(0xffffffffu, tmax_hi, 2));

        float mnew_lo = fmaxf(m_lo, tmax_lo);
        float mnew_hi = fmaxf(m_hi, tmax_hi);
        float al = __expf(m_lo - mnew_lo);
        float ah = __expf(m_hi - mnew_hi);
        m_lo = mnew_lo; m_hi = mnew_hi;

        // ---- p = exp(s - m), partial row sums ----
        float ps_lo = 0.f, ps_hi = 0.f;
#pragma unroll
        for (int nt = 0; nt < 4; nt++) {
#pragma unroll
            for (int c = 0; c < 4; c++) {
                float s = sc[nt][c];
                float mm = (c < 2) ? m_lo : m_hi;
                float pv = (s > -1e29f) ? __expf(s - mm) : 0.f;
                sc[nt][c] = pv;
                if (c < 2) ps_lo += pv; else ps_hi += pv;
            }
        }
        l_lo = l_lo * al + ps_lo;
        l_hi = l_hi * ah + ps_hi;

        // ---- rescale O ----
#pragma unroll
        for (int nt = 0; nt < 32; nt++) {
            o[nt][0] *= al; o[nt][1] *= al;
            o[nt][2] *= ah; o[nt][3] *= ah;
        }

        // ---- PV: O += P * V ----
        const int src0 = (lane & ~3) | (tig >> 1);
        const int src1 = src0 + 2;
#pragma unroll
        for (int kk = 0; kk < 4; kk++) {
            // permute C-fragment p (cols 2tig,2tig+1) into A-fragment (cols tig, tig+4)
            float s0 = __shfl_sync(0xffffffffu, sc[kk][0], src0);
            float s1 = __shfl_sync(0xffffffffu, sc[kk][1], src0);
            float s2 = __shfl_sync(0xffffffffu, sc[kk][2], src0);
            float s3 = __shfl_sync(0xffffffffu, sc[kk][3], src0);
            float u0 = __shfl_sync(0xffffffffu, sc[kk][0], src1);
            float u1 = __shfl_sync(0xffffffffu, sc[kk][1], src1);
            float u2 = __shfl_sync(0xffffffffu, sc[kk][2], src1);
            float u3 = __shfl_sync(0xffffffffu, sc[kk][3], src1);
            unsigned a0 = f2tf((tig & 1) ? s1 : s0);   // row lo, k = kk*8+tig
            unsigned a1 = f2tf((tig & 1) ? s3 : s2);   // row hi, k = kk*8+tig
            unsigned a2 = f2tf((tig & 1) ? u1 : u0);   // row lo, k = kk*8+tig+4
            unsigned a3 = f2tf((tig & 1) ? u3 : u2);   // row hi, k = kk*8+tig+4
#pragma unroll
            for (int nt = 0; nt < 32; nt++) {
                unsigned b0 = Vs[(kk * 8 + tig) * VPITCH + nt * 8 + g];
                unsigned b1 = Vs[(kk * 8 + tig + 4) * VPITCH + nt * 8 + g];
                mma_tf32(o[nt][0], o[nt][1], o[nt][2], o[nt][3],
                         a0, a1, a2, a3, b0, b1);
            }
        }
    }

    // ---- final row-sum reduce + normalize + write ----
    l_lo += __shfl_xor_sync(0xffffffffu, l_lo, 1);
    l_lo += __shfl_xor_sync(0xffffffffu, l_lo, 2);
    l_hi += __shfl_xor_sync(0xffffffffu, l_hi, 1);
    l_hi += __shfl_xor_sync(0xffffffffu, l_hi, 2);
    float inv_lo = 1.0f / l_lo;
    float inv_hi = 1.0f / l_hi;

#pragma unroll
    for (int nt = 0; nt < 32; nt++) {
        int col = h * HD + nt * 8 + 2 * tig;
        *(float2*)&out[(size_t)qi_lo * QDIM + col] = make_float2(o[nt][0] * inv_lo, o[nt][1] * inv_lo);
        *(float2*)&out[(size_t)qi_hi * QDIM + col] = make_float2(o[nt][2] * inv_hi, o[nt][3] * inv_hi);
    }
}

// ---------------------------------------------------------------------------
// Launch
// ---------------------------------------------------------------------------
extern "C" void kernel_launch(void* const* d_in, const int* in_sizes, int n_in,
                              void* d_out, int out_size) {
    const float* x   = (const float*)d_in[0];
    const int*   pos = (const int*)  d_in[1];
    const float* Wq  = (const float*)d_in[2];
    const float* Wk  = (const float*)d_in[3];
    const float* Wv  = (const float*)d_in[4];
    const float* Wo  = (const float*)d_in[5];
    float* out = (float*)d_out;

    float *q, *k, *v, *ao;
    cudaGetSymbolAddress((void**)&q,  g_q);
    cudaGetSymbolAddress((void**)&k,  g_k);
    cudaGetSymbolAddress((void**)&v,  g_v);
    cudaGetSymbolAddress((void**)&ao, g_ao);

    // QKV projections (tf32 tensor-core GEMMs)
    gemm_tf32<<<dim3(QDIM / 64,  S_LEN / 128), 128>>>(x, Wq, q, S_LEN, QDIM,  HID);
    gemm_tf32<<<dim3(KVDIM / 64, S_LEN / 128), 128>>>(x, Wk, k, S_LEN, KVDIM, HID);
    gemm_tf32<<<dim3(KVDIM / 64, S_LEN / 128), 128>>>(x, Wv, v, S_LEN, KVDIM, HID);

    // RoPE in place
    rope_kernel<<<S_LEN, 256>>>(pos);

    // Flash attention (tf32 tensor-core)
    size_t smem = (size_t)(64 * QPITCH + 32 * KPITCH + 32 * VPITCH) * sizeof(unsigned);
    cudaFuncSetAttribute(attn_tf32, cudaFuncAttributeMaxDynamicSharedMemorySize, (int)smem);
    attn_tf32<<<dim3(S_LEN / BQ, NH), 128, smem>>>(ao);

    // Output projection
    gemm_tf32<<<dim3(HID / 64, S_LEN / 128), 128>>>(ao, Wo, out, S_LEN, HID, QDIM);
}

// round 6
// speedup vs baseline: 4.0559x; 1.1244x over previous
#include <cuda_runtime.h>
#include <math.h>

#define S_LEN 4096
#define HID 2304
#define NH 8
#define NKV 4
#define HD 256
#define QDIM 2048
#define KVDIM 1024
#define SWIN 2048
#define ATTN_SCALE 0.0625f

__device__ float g_q [S_LEN*QDIM];
__device__ float g_k [S_LEN*KVDIM];
__device__ float g_v [S_LEN*KVDIM];
__device__ float g_vt[KVDIM*S_LEN];
__device__ float g_ao[S_LEN*QDIM];
__device__ float g_x [S_LEN*HID];
__device__ float g_wq[QDIM*HID];
__device__ float g_wk[KVDIM*HID];
__device__ float g_wv[KVDIM*HID];
__device__ float g_wo[HID*QDIM];

__device__ __forceinline__ unsigned f2tf(float f) {
    unsigned u; asm("cvt.rna.tf32.f32 %0, %1;" : "=r"(u) : "f"(f)); return u;
}
__device__ __forceinline__ unsigned s2u(const void* p) {
    return (unsigned)__cvta_generic_to_shared(p);
}
__device__ __forceinline__ void ldsm4(unsigned& r0, unsigned& r1, unsigned& r2, unsigned& r3, unsigned a) {
    asm volatile("ldmatrix.sync.aligned.m8n8.x4.shared.b16 {%0,%1,%2,%3},[%4];"
                 : "=r"(r0), "=r"(r1), "=r"(r2), "=r"(r3) : "r"(a));
}
__device__ __forceinline__ void cpa16(unsigned d, const float* s) {
    asm volatile("cp.async.cg.shared.global [%0],[%1],16;" :: "r"(d), "l"(s));
}
#define CP_COMMIT() asm volatile("cp.async.commit_group;")
#define CP_WAIT0()  asm volatile("cp.async.wait_group 0;")

__device__ __forceinline__ void mma_tf32(float& c0, float& c1, float& c2, float& c3,
        unsigned a0, unsigned a1, unsigned a2, unsigned a3, unsigned b0, unsigned b1) {
    asm volatile("mma.sync.aligned.m16n8k8.row.col.f32.tf32.tf32.f32 "
        "{%0,%1,%2,%3},{%4,%5,%6,%7},{%8,%9},{%0,%1,%2,%3};\n"
        : "+f"(c0), "+f"(c1), "+f"(c2), "+f"(c3)
        : "r"(a0), "r"(a1), "r"(a2), "r"(a3), "r"(b0), "r"(b1));
}

__global__ __launch_bounds__(256) void round_copy(float* __restrict__ d, const float* __restrict__ s, int n4) {
    int i = blockIdx.x * 256 + threadIdx.x;
    if (i < n4) {
        float4 v = ((const float4*)s)[i];
        ((uint4*)d)[i] = make_uint4(f2tf(v.x), f2tf(v.y), f2tf(v.z), f2tf(v.w));
    }
}

__global__ __launch_bounds__(256) void transpose_round_v() {
    __shared__ float tile[32][33];
    int s0 = blockIdx.x * 32, d0 = blockIdx.y * 32;
    int tx = threadIdx.x & 31, ty = threadIdx.x >> 5;
#pragma unroll
    for (int i = 0; i < 4; i++)
        tile[ty + 8*i][tx] = g_v[(size_t)(s0 + ty + 8*i) * KVDIM + d0 + tx];
    __syncthreads();
#pragma unroll
    for (int i = 0; i < 4; i++)
        g_vt[(size_t)(d0 + ty + 8*i) * S_LEN + s0 + tx] = __uint_as_float(f2tf(tile[tx][ty + 8*i]));
}

__global__ __launch_bounds__(256) void rope_kernel(const int* __restrict__ pos) {
    __shared__ float cs[128], sn[128];
    const int s = blockIdx.x, t = threadIdx.x;
    const float p = (float)pos[s];
    if (t < 128) {
        float invf = 1.0f / powf(10000.0f, (float)(2 * t) / 256.0f);
        sincosf(p * invf, &sn[t], &cs[t]);
    }
    __syncthreads();
    for (int idx = t; idx < (NH + NKV) * 128; idx += 256) {
        int h = idx >> 7, d = idx & 127;
        float c = cs[d], ss = sn[d];
        float* b = (h < NH) ? (g_q + (size_t)s * QDIM + h * HD)
                            : (g_k + (size_t)s * KVDIM + (h - NH) * HD);
        float x1 = b[d], x2 = b[d + 128];
        b[d]       = __uint_as_float(f2tf(x1 * c - x2 * ss));
        b[d + 128] = __uint_as_float(f2tf(x2 * c + x1 * ss));
    }
}

// ---------------- GEMM: C = A[M,K] * B[N,K]^T (inputs pre-rounded tf32) -----
#define GKP 36
__device__ __forceinline__ void gemm_issue(unsigned sa, unsigned sb,
        const float* __restrict__ A, const float* __restrict__ B,
        int m0, int n0, int K, int k0, int r0w, int cw) {
#pragma unroll
    for (int i = 0; i < 8; i++) {
        int r = r0w + 16 * i;
        cpa16(sa + (unsigned)((r * GKP + cw) * 4), A + (size_t)(m0 + r) * K + k0 + cw);
        cpa16(sb + (unsigned)((r * GKP + cw) * 4), B + (size_t)(n0 + r) * K + k0 + cw);
    }
    CP_COMMIT();
}

__global__ __launch_bounds__(128) void gemm_tc(const float* __restrict__ A,
        const float* __restrict__ B, float* __restrict__ C, int M, int N, int K) {
    extern __shared__ float smf[];
    const int t = threadIdx.x, lane = t & 31, wid = t >> 5;
    const int g = lane >> 2, tig = lane & 3;
    const int wm = (wid >> 1) * 64, wn = (wid & 1) * 64;
    const int m0 = blockIdx.y * 128, n0 = blockIdx.x * 128;
    const unsigned sb0 = s2u(smf);
    const unsigned sA0 = sb0, sA1 = sb0 + 128u*GKP*4u;
    const unsigned sB0 = sb0 + 2u*128u*GKP*4u, sB1 = sb0 + 3u*128u*GKP*4u;
    const int r0w = t >> 3, cw = (t & 7) * 4;
    const int lrow = (lane & 7) + ((lane >> 4) & 1) * 8;
    const int lcol = ((lane >> 3) & 1) * 4;

    float acc[4][8][4];
#pragma unroll
    for (int mt = 0; mt < 4; mt++)
#pragma unroll
        for (int nt = 0; nt < 8; nt++)
#pragma unroll
            for (int c = 0; c < 4; c++) acc[mt][nt][c] = 0.f;

    const int nch = K >> 5;
    gemm_issue(sA0, sB0, A, B, m0, n0, K, 0, r0w, cw);
    for (int ci = 0; ci < nch; ci++) {
        CP_WAIT0();
        __syncthreads();
        if (ci + 1 < nch)
            gemm_issue((ci & 1) ? sA0 : sA1, (ci & 1) ? sB0 : sB1, A, B, m0, n0, K, (ci + 1) << 5, r0w, cw);
        const unsigned sa = (ci & 1) ? sA1 : sA0;
        const unsigned sbb = (ci & 1) ? sB1 : sB0;
#pragma unroll
        for (int ks = 0; ks < 32; ks += 8) {
            unsigned a[4][4], b[4][4];
#pragma unroll
            for (int mt = 0; mt < 4; mt++)
                ldsm4(a[mt][0], a[mt][1], a[mt][2], a[mt][3],
                      sa + (unsigned)(((wm + mt*16 + lrow) * GKP + ks + lcol) * 4));
#pragma unroll
            for (int p = 0; p < 4; p++)
                ldsm4(b[p][0], b[p][1], b[p][2], b[p][3],
                      sbb + (unsigned)(((wn + p*16 + lrow) * GKP + ks + lcol) * 4));
#pragma unroll
            for (int nt = 0; nt < 8; nt++) {
                unsigned b0 = b[nt >> 1][(nt & 1) * 2], b1 = b[nt >> 1][(nt & 1) * 2 + 1];
#pragma unroll
                for (int mt = 0; mt < 4; mt++)
                    mma_tf32(acc[mt][nt][0], acc[mt][nt][1], acc[mt][nt][2], acc[mt][nt][3],
                             a[mt][0], a[mt][2], a[mt][1], a[mt][3], b0, b1);
            }
        }
    }
#pragma unroll
    for (int mt = 0; mt < 4; mt++) {
        int row = m0 + wm + mt * 16 + g;
#pragma unroll
        for (int nt = 0; nt < 8; nt++) {
            int col = n0 + wn + nt * 8 + 2 * tig;
            *(float2*)&C[(size_t)row * N + col]       = make_float2(acc[mt][nt][0], acc[mt][nt][1]);
            *(float2*)&C[(size_t)(row + 8) * N + col] = make_float2(acc[mt][nt][2], acc[mt][nt][3]);
        }
    }
}

// ---------------- Flash attention -------------------------------------------
#define BQ 64
#define BK 32
#define AQP 260
#define AVP 36

__device__ __forceinline__ void attn_issue(unsigned sk, unsigned sv, int j0, int hkv, int t) {
#pragma unroll
    for (int i = 0; i < 16; i++) {
        int c = t + 128 * i;
        int r = c >> 6, col = (c & 63) * 4;
        cpa16(sk + (unsigned)((r * AQP + col) * 4), g_k + (size_t)(j0 + r) * KVDIM + hkv * HD + col);
    }
#pragma unroll
    for (int i = 0; i < 16; i++) {
        int c = t + 128 * i;
        int r = c >> 3, col = (c & 7) * 4;
        cpa16(sv + (unsigned)((r * AVP + col) * 4), g_vt + (size_t)(hkv * HD + r) * S_LEN + j0 + col);
    }
    CP_COMMIT();
}

__global__ __launch_bounds__(128, 1) void attn_tc(float* __restrict__ out) {
    extern __shared__ float smf[];
    const unsigned sb0 = s2u(smf);
    const unsigned sQ  = sb0;
    const unsigned sK0 = sb0 + 64u*AQP*4u, sK1 = sK0 + 32u*AQP*4u;
    const unsigned sV0 = sK1 + 32u*AQP*4u, sV1 = sV0 + 256u*AVP*4u;
    float* Qs = smf;

    const int t = threadIdx.x, lane = t & 31, wid = t >> 5;
    const int g = lane >> 2, tig = lane & 3;
    const int h = blockIdx.y;
    const int q0 = (int)(gridDim.x - 1 - blockIdx.x) * BQ;
    const int hkv = h >> 1;
    const int rbase = wid * 16;
    const int qi_lo = q0 + rbase + g, qi_hi = qi_lo + 8;
    const int lrow = (lane & 7) + ((lane >> 4) & 1) * 8;
    const int lcol = ((lane >> 3) & 1) * 4;

    int jlo = q0 - (SWIN - 1); if (jlo < 0) jlo = 0;
    const int jstart = jlo & ~(BK - 1);
    const int ntiles = (q0 + BQ - jstart) / BK;

    attn_issue(sK0, sV0, jstart, hkv, t);
    for (int i = t; i < 64 * 64; i += 128) {
        int r = i >> 6, c = (i & 63) * 4;
        *(float4*)&Qs[r * AQP + c] = *(const float4*)&g_q[(size_t)(q0 + r) * QDIM + h * HD + c];
    }

    float o[32][4];
#pragma unroll
    for (int nt = 0; nt < 32; nt++)
#pragma unroll
        for (int c = 0; c < 4; c++) o[nt][c] = 0.f;
    float m_lo = -1e30f, m_hi = -1e30f, l_lo = 0.f, l_hi = 0.f;

    for (int ci = 0; ci < ntiles; ci++) {
        const int j0 = jstart + ci * BK;
        CP_WAIT0();
        __syncthreads();
        if (ci + 1 < ntiles)
            attn_issue((ci & 1) ? sK0 : sK1, (ci & 1) ? sV0 : sV1, j0 + BK, hkv, t);
        const unsigned sk = (ci & 1) ? sK1 : sK0;
        const unsigned sv = (ci & 1) ? sV1 : sV0;

        float sc[4][4];
#pragma unroll
        for (int nt = 0; nt < 4; nt++)
#pragma unroll
            for (int c = 0; c < 4; c++) sc[nt][c] = 0.f;

#pragma unroll 4
        for (int ks = 0; ks < 256; ks += 8) {
            unsigned qa0, qa1, qa2, qa3;
            ldsm4(qa0, qa1, qa2, qa3, sQ + (unsigned)(((rbase + lrow) * AQP + ks + lcol) * 4));
            unsigned kb[2][4];
#pragma unroll
            for (int p = 0; p < 2; p++)
                ldsm4(kb[p][0], kb[p][1], kb[p][2], kb[p][3],
                      sk + (unsigned)(((p * 16 + lrow) * AQP + ks + lcol) * 4));
#pragma unroll
            for (int nt = 0; nt < 4; nt++) {
                unsigned b0 = kb[nt >> 1][(nt & 1) * 2], b1 = kb[nt >> 1][(nt & 1) * 2 + 1];
                mma_tf32(sc[nt][0], sc[nt][1], sc[nt][2], sc[nt][3], qa0, qa2, qa1, qa3, b0, b1);
            }
        }

        float tmax_lo = -1e30f, tmax_hi = -1e30f;
#pragma unroll
        for (int nt = 0; nt < 4; nt++) {
#pragma unroll
            for (int c = 0; c < 4; c++) {
                int j = j0 + nt * 8 + 2 * tig + (c & 1);
                int qi = (c < 2) ? qi_lo : qi_hi;
                float s = sc[nt][c] * (ATTN_SCALE / 50.0f);      // s/softcap
                float e = __expf(2.0f * s);
                s = 50.0f * (1.0f - __fdividef(2.0f, e + 1.0f)); // 50*tanh
                bool valid = (j <= qi) && ((qi - j) < SWIN);
                s = valid ? s : -1e30f;
                sc[nt][c] = s;
                if (c < 2) tmax_lo = fmaxf(tmax_lo, s); else tmax_hi = fmaxf(tmax_hi, s);
            }
        }
        tmax_lo = fmaxf(tmax_lo, __shfl_xor_sync(0xffffffffu, tmax_lo, 1));
        tmax_lo = fmaxf(tmax_lo, __shfl_xor_sync(0xffffffffu, tmax_lo, 2));
        tmax_hi = fmaxf(tmax_hi, __shfl_xor_sync(0xffffffffu, tmax_hi, 1));
        tmax_hi = fmaxf(tmax_hi, __shfl_xor_sync(0xffffffffu, tmax_hi, 2));
        float mn_lo = fmaxf(m_lo, tmax_lo), mn_hi = fmaxf(m_hi, tmax_hi);
        float al = __expf(m_lo - mn_lo), ah = __expf(m_hi - mn_hi);
        m_lo = mn_lo; m_hi = mn_hi;

        float ps_lo = 0.f, ps_hi = 0.f;
#pragma unroll
        for (int nt = 0; nt < 4; nt++) {
#pragma unroll
            for (int c = 0; c < 4; c++) {
                float s = sc[nt][c];
                float mm = (c < 2) ? m_lo : m_hi;
                float pv = (s > -1e29f) ? __expf(s - mm) : 0.f;
                sc[nt][c] = pv;
                if (c < 2) ps_lo += pv; else ps_hi += pv;
            }
        }
        l_lo = l_lo * al + ps_lo;
        l_hi = l_hi * ah + ps_hi;
#pragma unroll
        for (int nt = 0; nt < 32; nt++) {
            o[nt][0] *= al; o[nt][1] *= al; o[nt][2] *= ah; o[nt][3] *= ah;
        }

        const int src0 = (lane & ~3) | (tig >> 1);
        const int src1 = src0 + 2;
#pragma unroll
        for (int kk = 0; kk < 4; kk++) {
            float s0 = __shfl_sync(0xffffffffu, sc[kk][0], src0);
            float s1 = __shfl_sync(0xffffffffu, sc[kk][1], src0);
            float s2 = __shfl_sync(0xffffffffu, sc[kk][2], src0);
            float s3 = __shfl_sync(0xffffffffu, sc[kk][3], src0);
            float u0 = __shfl_sync(0xffffffffu, sc[kk][0], src1);
            float u1 = __shfl_sync(0xffffffffu, sc[kk][1], src1);
            float u2 = __shfl_sync(0xffffffffu, sc[kk][2], src1);
            float u3 = __shfl_sync(0xffffffffu, sc[kk][3], src1);
            unsigned a0 = f2tf((tig & 1) ? s1 : s0);
            unsigned a1 = f2tf((tig & 1) ? s3 : s2);
            unsigned a2 = f2tf((tig & 1) ? u1 : u0);
            unsigned a3 = f2tf((tig & 1) ? u3 : u2);
#pragma unroll
            for (int p = 0; p < 16; p++) {
                unsigned v0, v1, v2, v3;
                ldsm4(v0, v1, v2, v3, sv + (unsigned)(((p * 16 + lrow) * AVP + kk * 8 + lcol) * 4));
                mma_tf32(o[2*p][0],   o[2*p][1],   o[2*p][2],   o[2*p][3],   a0, a1, a2, a3, v0, v1);
                mma_tf32(o[2*p+1][0], o[2*p+1][1], o[2*p+1][2], o[2*p+1][3], a0, a1, a2, a3, v2, v3);
            }
        }
    }

    l_lo += __shfl_xor_sync(0xffffffffu, l_lo, 1);
    l_lo += __shfl_xor_sync(0xffffffffu, l_lo, 2);
    l_hi += __shfl_xor_sync(0xffffffffu, l_hi, 1);
    l_hi += __shfl_xor_sync(0xffffffffu, l_hi, 2);
    float inv_lo = 1.0f / l_lo, inv_hi = 1.0f / l_hi;
#pragma unroll
    for (int nt = 0; nt < 32; nt++) {
        int col = h * HD + nt * 8 + 2 * tig;
        float2 lo = make_float2(__uint_as_float(f2tf(o[nt][0] * inv_lo)), __uint_as_float(f2tf(o[nt][1] * inv_lo)));
        float2 hi = make_float2(__uint_as_float(f2tf(o[nt][2] * inv_hi)), __uint_as_float(f2tf(o[nt][3] * inv_hi)));
        *(float2*)&out[(size_t)qi_lo * QDIM + col] = lo;
        *(float2*)&out[(size_t)qi_hi * QDIM + col] = hi;
    }
}

extern "C" void kernel_launch(void* const* d_in, const int* in_sizes, int n_in,
                              void* d_out, int out_size) {
    const float* x   = (const float*)d_in[0];
    const int*   pos = (const int*)  d_in[1];
    const float* Wq  = (const float*)d_in[2];
    const float* Wk  = (const float*)d_in[3];
    const float* Wv  = (const float*)d_in[4];
    const float* Wo  = (const float*)d_in[5];
    float* out = (float*)d_out;

    float *q, *k, *v, *vt, *ao, *rx, *rwq, *rwk, *rwv, *rwo;
    cudaGetSymbolAddress((void**)&q,   g_q);
    cudaGetSymbolAddress((void**)&k,   g_k);
    cudaGetSymbolAddress((void**)&v,   g_v);
    cudaGetSymbolAddress((void**)&vt,  g_vt);
    cudaGetSymbolAddress((void**)&ao,  g_ao);
    cudaGetSymbolAddress((void**)&rx,  g_x);
    cudaGetSymbolAddress((void**)&rwq, g_wq);
    cudaGetSymbolAddress((void**)&rwk, g_wk);
    cudaGetSymbolAddress((void**)&rwv, g_wv);
    cudaGetSymbolAddress((void**)&rwo, g_wo);

    round_copy<<<S_LEN*HID/1024, 256>>>(rx,  x,  S_LEN*HID/4);
    round_copy<<<QDIM*HID/1024,  256>>>(rwq, Wq, QDIM*HID/4);
    round_copy<<<KVDIM*HID/1024, 256>>>(rwk, Wk, KVDIM*HID/4);
    round_copy<<<KVDIM*HID/1024, 256>>>(rwv, Wv, KVDIM*HID/4);
    round_copy<<<HID*QDIM/1024,  256>>>(rwo, Wo, HID*QDIM/4);

    int gsm = 4 * 128 * GKP * 4;
    cudaFuncSetAttribute(gemm_tc, cudaFuncAttributeMaxDynamicSharedMemorySize, gsm);
    gemm_tc<<<dim3(QDIM/128,  S_LEN/128), 128, gsm>>>(rx, rwq, q, S_LEN, QDIM,  HID);
    gemm_tc<<<dim3(KVDIM/128, S_LEN/128), 128, gsm>>>(rx, rwk, k, S_LEN, KVDIM, HID);
    gemm_tc<<<dim3(KVDIM/128, S_LEN/128), 128, gsm>>>(rx, rwv, v, S_LEN, KVDIM, HID);

    rope_kernel<<<S_LEN, 256>>>(pos);
    transpose_round_v<<<dim3(S_LEN/32, KVDIM/32), 256>>>();

    int asm_ = (64*AQP + 2*32*AQP + 2*256*AVP) * 4;
    cudaFuncSetAttribute(attn_tc, cudaFuncAttributeMaxDynamicSharedMemorySize, asm_);
    attn_tc<<<dim3(S_LEN/BQ, NH), 128, asm_>>>(ao);

    gemm_tc<<<dim3(HID/128, S_LEN/128), 128, gsm>>>(ao, rwo, out, S_LEN, HID, QDIM);
}

// round 8
// speedup vs baseline: 4.3754x; 1.0788x over previous
#include <cuda_runtime.h>
#include <math.h>

#define S_LEN 4096
#define HID 2304
#define NH 8
#define NKV 4
#define HD 256
#define QDIM 2048
#define KVDIM 1024
#define SWIN 2048
#define ATTN_SCALE 0.0625f

__device__ float g_q [S_LEN*QDIM];
__device__ float g_k [S_LEN*KVDIM];
__device__ float g_v [S_LEN*KVDIM];
__device__ float g_vt[KVDIM*S_LEN];
__device__ float g_ao[S_LEN*QDIM];
__device__ float g_x [S_LEN*HID];
__device__ float g_wq[QDIM*HID];
__device__ float g_wk[KVDIM*HID];
__device__ float g_wv[KVDIM*HID];
__device__ float g_wo[HID*QDIM];

__device__ __forceinline__ unsigned f2tf(float f) {
    unsigned u; asm("cvt.rna.tf32.f32 %0, %1;" : "=r"(u) : "f"(f)); return u;
}
__device__ __forceinline__ unsigned s2u(const void* p) {
    return (unsigned)__cvta_generic_to_shared(p);
}
__device__ __forceinline__ void ldsm4(unsigned& r0, unsigned& r1, unsigned& r2, unsigned& r3, unsigned a) {
    asm volatile("ldmatrix.sync.aligned.m8n8.x4.shared.b16 {%0,%1,%2,%3},[%4];"
                 : "=r"(r0), "=r"(r1), "=r"(r2), "=r"(r3) : "r"(a));
}
__device__ __forceinline__ void cpa16(unsigned d, const float* s) {
    asm volatile("cp.async.cg.shared.global [%0],[%1],16;" :: "r"(d), "l"(s));
}
#define CP_COMMIT() asm volatile("cp.async.commit_group;")
#define CP_WAIT0()  asm volatile("cp.async.wait_group 0;")
#define CP_WAIT1()  asm volatile("cp.async.wait_group 1;")

__device__ __forceinline__ void mma_tf32(float& c0, float& c1, float& c2, float& c3,
        unsigned a0, unsigned a1, unsigned a2, unsigned a3, unsigned b0, unsigned b1) {
    asm volatile("mma.sync.aligned.m16n8k8.row.col.f32.tf32.tf32.f32 "
        "{%0,%1,%2,%3},{%4,%5,%6,%7},{%8,%9},{%0,%1,%2,%3};\n"
        : "+f"(c0), "+f"(c1), "+f"(c2), "+f"(c3)
        : "r"(a0), "r"(a1), "r"(a2), "r"(a3), "r"(b0), "r"(b1));
}

__global__ __launch_bounds__(256) void round_copy(float* __restrict__ d, const float* __restrict__ s, int n4) {
    int i = blockIdx.x * 256 + threadIdx.x;
    if (i < n4) {
        float4 v = ((const float4*)s)[i];
        ((uint4*)d)[i] = make_uint4(f2tf(v.x), f2tf(v.y), f2tf(v.z), f2tf(v.w));
    }
}

// round all three qkv weights in one launch.
// FIXED boundaries: wq = QDIM*HID/4 = 1179648 f4, wk/wv = KVDIM*HID/4 = 589824 f4 each.
// total = 2359296 f4 -> grid 9216 x 256.
__global__ __launch_bounds__(256) void round_w3(const float* __restrict__ wq,
        const float* __restrict__ wk, const float* __restrict__ wv) {
    int i = blockIdx.x * 256 + threadIdx.x;
    const float* s; float* d; int off;
    if (i < 1179648)      { s = wq; d = g_wq; off = i; }
    else if (i < 1769472) { s = wk; d = g_wk; off = i - 1179648; }
    else                  { s = wv; d = g_wv; off = i - 1769472; }
    float4 v = ((const float4*)s)[off];
    ((uint4*)d)[off] = make_uint4(f2tf(v.x), f2tf(v.y), f2tf(v.z), f2tf(v.w));
}

__global__ __launch_bounds__(256) void transpose_round_v() {
    __shared__ float tile[32][33];
    int s0 = blockIdx.x * 32, d0 = blockIdx.y * 32;
    int tx = threadIdx.x & 31, ty = threadIdx.x >> 5;
#pragma unroll
    for (int i = 0; i < 4; i++)
        tile[ty + 8*i][tx] = g_v[(size_t)(s0 + ty + 8*i) * KVDIM + d0 + tx];
    __syncthreads();
#pragma unroll
    for (int i = 0; i < 4; i++)
        g_vt[(size_t)(d0 + ty + 8*i) * S_LEN + s0 + tx] = __uint_as_float(f2tf(tile[tx][ty + 8*i]));
}

__global__ __launch_bounds__(256) void rope_kernel(const int* __restrict__ pos) {
    __shared__ float cs[128], sn[128];
    const int s = blockIdx.x, t = threadIdx.x;
    const float p = (float)pos[s];
    if (t < 128) {
        float invf = 1.0f / powf(10000.0f, (float)(2 * t) / 256.0f);
        sincosf(p * invf, &sn[t], &cs[t]);
    }
    __syncthreads();
    for (int idx = t; idx < (NH + NKV) * 128; idx += 256) {
        int h = idx >> 7, d = idx & 127;
        float c = cs[d], ss = sn[d];
        float* b = (h < NH) ? (g_q + (size_t)s * QDIM + h * HD)
                            : (g_k + (size_t)s * KVDIM + (h - NH) * HD);
        float x1 = b[d], x2 = b[d + 128];
        b[d]       = __uint_as_float(f2tf(x1 * c - x2 * ss));
        b[d + 128] = __uint_as_float(f2tf(x2 * c + x1 * ss));
    }
}

// ---------------- GEMM core (128 thr, 128x128 tile, 3-stage cp.async) ------
#define GKP 36
__device__ __forceinline__ void g3_issue(unsigned sa, unsigned sb,
        const float* __restrict__ A, const float* __restrict__ B,
        int m0, int bn0, int K, int k0, int r0w, int cw) {
#pragma unroll
    for (int i = 0; i < 8; i++) {
        int r = r0w + 16 * i;
        cpa16(sa + (unsigned)((r * GKP + cw) * 4), A + (size_t)(m0 + r) * K + k0 + cw);
        cpa16(sb + (unsigned)((r * GKP + cw) * 4), B + (size_t)(bn0 + r) * K + k0 + cw);
    }
    CP_COMMIT();
}

// QKV==1: fused projection with output routing; QKV==0: plain C=A*B^T
template<int QKV>
__global__ __launch_bounds__(128) void gemm3(const float* __restrict__ A,
        const float* __restrict__ B_, float* __restrict__ C_, int N, int K) {
    extern __shared__ float smf[];
    const int t = threadIdx.x, lane = t & 31, wid = t >> 5;
    const int g = lane >> 2, tig = lane & 3;
    const int wm = (wid >> 1) * 64, wn = (wid & 1) * 64;
    const int m0 = blockIdx.y * 128, n0 = blockIdx.x * 128;
    const unsigned sb0 = s2u(smf);
    const unsigned STG = 128u * GKP * 4u;
    const int r0w = t >> 3, cw = (t & 7) * 4;
    const int lrow = (lane & 7) + ((lane >> 4) & 1) * 8;
    const int lcol = ((lane >> 3) & 1) * 4;

    const float* B; float* C; int bn0, Nld;
    if (QKV) {
        if (n0 < 2048)      { B = g_wq; C = g_q; bn0 = n0;        Nld = 2048; }
        else if (n0 < 3072) { B = g_wk; C = g_k; bn0 = n0 - 2048; Nld = 1024; }
        else                { B = g_wv; C = g_v; bn0 = n0 - 3072; Nld = 1024; }
    } else { B = B_; C = C_; bn0 = n0; Nld = N; }

    float acc[4][8][4];
#pragma unroll
    for (int mt = 0; mt < 4; mt++)
#pragma unroll
        for (int nt = 0; nt < 8; nt++)
#pragma unroll
            for (int c = 0; c < 4; c++) acc[mt][nt][c] = 0.f;

    const int nch = K >> 5;
    g3_issue(sb0, sb0 + 3u*STG, A, B, m0, bn0, K, 0, r0w, cw);
    g3_issue(sb0 + STG, sb0 + 4u*STG, A, B, m0, bn0, K, 32, r0w, cw);
    for (int ci = 0; ci < nch; ci++) {
        if (ci + 1 < nch) { CP_WAIT1(); } else { CP_WAIT0(); }
        __syncthreads();
        if (ci + 2 < nch) {
            int s = (ci + 2) % 3;
            g3_issue(sb0 + (unsigned)s*STG, sb0 + (unsigned)(s+3)*STG, A, B, m0, bn0, K, (ci + 2) << 5, r0w, cw);
        }
        const unsigned sa = sb0 + (unsigned)(ci % 3) * STG;
        const unsigned sbb = sb0 + (unsigned)(ci % 3 + 3) * STG;
#pragma unroll
        for (int ks = 0; ks < 32; ks += 8) {
            unsigned a[4][4], b[4][4];
#pragma unroll
            for (int mt = 0; mt < 4; mt++)
                ldsm4(a[mt][0], a[mt][1], a[mt][2], a[mt][3],
                      sa + (unsigned)(((wm + mt*16 + lrow) * GKP + ks + lcol) * 4));
#pragma unroll
            for (int p = 0; p < 4; p++)
                ldsm4(b[p][0], b[p][1], b[p][2], b[p][3],
                      sbb + (unsigned)(((wn + p*16 + lrow) * GKP + ks + lcol) * 4));
#pragma unroll
            for (int nt = 0; nt < 8; nt++) {
                unsigned b0 = b[nt >> 1][(nt & 1) * 2], b1 = b[nt >> 1][(nt & 1) * 2 + 1];
#pragma unroll
                for (int mt = 0; mt < 4; mt++)
                    mma_tf32(acc[mt][nt][0], acc[mt][nt][1], acc[mt][nt][2], acc[mt][nt][3],
                             a[mt][0], a[mt][2], a[mt][1], a[mt][3], b0, b1);
            }
        }
    }
#pragma unroll
    for (int mt = 0; mt < 4; mt++) {
        int row = m0 + wm + mt * 16 + g;
#pragma unroll
        for (int nt = 0; nt < 8; nt++) {
            int col = bn0 + wn + nt * 8 + 2 * tig;
            *(float2*)&C[(size_t)row * Nld + col]       = make_float2(acc[mt][nt][0], acc[mt][nt][1]);
            *(float2*)&C[(size_t)(row + 8) * Nld + col] = make_float2(acc[mt][nt][2], acc[mt][nt][3]);
        }
    }
}

// ---------------- Flash attention: 8 warps, split-HD warp pairs -------------
#define BQ 64
#define BK 32
#define AQP 260
#define AVP 36
#define SXOFF (64*AQP + 2*32*AQP + 2*256*AVP)   // 51712 words

__device__ __forceinline__ void attn_issue(unsigned sk, unsigned sv, int j0, int hkv, int t) {
#pragma unroll
    for (int i = 0; i < 8; i++) {
        int c = t + 256 * i;
        int r = c >> 6, col = (c & 63) * 4;
        cpa16(sk + (unsigned)((r * AQP + col) * 4), g_k + (size_t)(j0 + r) * KVDIM + hkv * HD + col);
    }
#pragma unroll
    for (int i = 0; i < 8; i++) {
        int c = t + 256 * i;
        int r = c >> 3, col = (c & 7) * 4;
        cpa16(sv + (unsigned)((r * AVP + col) * 4), g_vt + (size_t)(hkv * HD + r) * S_LEN + j0 + col);
    }
    CP_COMMIT();
}

__global__ __launch_bounds__(256, 1) void attn_tc(float* __restrict__ out) {
    extern __shared__ float smf[];
    const unsigned sb0 = s2u(smf);
    const unsigned sQ  = sb0;
    const unsigned sK0 = sb0 + 64u*AQP*4u, sK1 = sK0 + 32u*AQP*4u;
    const unsigned sV0 = sK1 + 32u*AQP*4u, sV1 = sV0 + 256u*AVP*4u;
    float* Qs = smf;
    float* Sx = smf + SXOFF;   // 8 warps x 512 words exchange

    const int t = threadIdx.x, lane = t & 31, wid = t >> 5;
    const int g = lane >> 2, tig = lane & 3;
    const int pairid = wid & 3, half = wid >> 2;
    const int h = blockIdx.y;
    const int q0 = (int)(gridDim.x - 1 - blockIdx.x) * BQ;
    const int hkv = h >> 1;
    const int rbase = pairid * 16;
    const int ksbase = half * 128;
    const int qi_lo = q0 + rbase + g, qi_hi = qi_lo + 8;
    const int lrow = (lane & 7) + ((lane >> 4) & 1) * 8;
    const int lcol = ((lane >> 3) & 1) * 4;
    float* myS   = Sx + wid * 512;
    float* peerS = Sx + (wid ^ 4) * 512;

    int jlo = q0 - (SWIN - 1); if (jlo < 0) jlo = 0;
    const int jstart = jlo & ~(BK - 1);
    const int ntiles = (q0 + BQ - jstart) / BK;

    attn_issue(sK0, sV0, jstart, hkv, t);
    for (int i = t; i < 64 * 64; i += 256) {
        int r = i >> 6, c = (i & 63) * 4;
        *(float4*)&Qs[r * AQP + c] = *(const float4*)&g_q[(size_t)(q0 + r) * QDIM + h * HD + c];
    }

    float o[16][4];
#pragma unroll
    for (int nt = 0; nt < 16; nt++)
#pragma unroll
        for (int c = 0; c < 4; c++) o[nt][c] = 0.f;
    float m_lo = -1e30f, m_hi = -1e30f, l_lo = 0.f, l_hi = 0.f;

    for (int ci = 0; ci < ntiles; ci++) {
        const int j0 = jstart + ci * BK;
        CP_WAIT0();
        __syncthreads();
        if (ci + 1 < ntiles)
            attn_issue((ci & 1) ? sK0 : sK1, (ci & 1) ? sV0 : sV1, j0 + BK, hkv, t);
        const unsigned sk = (ci & 1) ? sK1 : sK0;
        const unsigned sv = (ci & 1) ? sV1 : sV0;

        // ---- QK^T over this warp's half of HD ----
        float sc[4][4];
#pragma unroll
        for (int nt = 0; nt < 4; nt++)
#pragma unroll
            for (int c = 0; c < 4; c++) sc[nt][c] = 0.f;
#pragma unroll 4
        for (int ks = 0; ks < 128; ks += 8) {
            unsigned qa0, qa1, qa2, qa3;
            ldsm4(qa0, qa1, qa2, qa3, sQ + (unsigned)(((rbase + lrow) * AQP + ksbase + ks + lcol) * 4));
            unsigned kb[2][4];
#pragma unroll
            for (int p = 0; p < 2; p++)
                ldsm4(kb[p][0], kb[p][1], kb[p][2], kb[p][3],
                      sk + (unsigned)(((p * 16 + lrow) * AQP + ksbase + ks + lcol) * 4));
#pragma unroll
            for (int nt = 0; nt < 4; nt++) {
                unsigned b0 = kb[nt >> 1][(nt & 1) * 2], b1 = kb[nt >> 1][(nt & 1) * 2 + 1];
                mma_tf32(sc[nt][0], sc[nt][1], sc[nt][2], sc[nt][3], qa0, qa2, qa1, qa3, b0, b1);
            }
        }

        // ---- exchange partial scores with pair warp, sum ----
#pragma unroll
        for (int nt = 0; nt < 4; nt++)
#pragma unroll
            for (int c = 0; c < 4; c++)
                myS[(nt * 4 + c) * 32 + lane] = sc[nt][c];
        __syncthreads();
#pragma unroll
        for (int nt = 0; nt < 4; nt++)
#pragma unroll
            for (int c = 0; c < 4; c++)
                sc[nt][c] += peerS[(nt * 4 + c) * 32 + lane];

        // ---- softcap + mask + online softmax (identical in both pair warps) ----
        float tmax_lo = -1e30f, tmax_hi = -1e30f;
#pragma unroll
        for (int nt = 0; nt < 4; nt++) {
#pragma unroll
            for (int c = 0; c < 4; c++) {
                int j = j0 + nt * 8 + 2 * tig + (c & 1);
                int qi = (c < 2) ? qi_lo : qi_hi;
                float s = sc[nt][c] * (ATTN_SCALE / 50.0f);
                float e = __expf(2.0f * s);
                s = 50.0f * (1.0f - __fdividef(2.0f, e + 1.0f));
                bool valid = (j <= qi) && ((qi - j) < SWIN);
                s = valid ? s : -1e30f;
                sc[nt][c] = s;
                if (c < 2) tmax_lo = fmaxf(tmax_lo, s); else tmax_hi = fmaxf(tmax_hi, s);
            }
        }
        tmax_lo = fmaxf(tmax_lo, __shfl_xor_sync(0xffffffffu, tmax_lo, 1));
        tmax_lo = fmaxf(tmax_lo, __shfl_xor_sync(0xffffffffu, tmax_lo, 2));
        tmax_hi = fmaxf(tmax_hi, __shfl_xor_sync(0xffffffffu, tmax_hi, 1));
        tmax_hi = fmaxf(tmax_hi, __shfl_xor_sync(0xffffffffu, tmax_hi, 2));
        float mn_lo = fmaxf(m_lo, tmax_lo), mn_hi = fmaxf(m_hi, tmax_hi);
        float al = __expf(m_lo - mn_lo), ah = __expf(m_hi - mn_hi);
        m_lo = mn_lo; m_hi = mn_hi;

        float ps_lo = 0.f, ps_hi = 0.f;
#pragma unroll
        for (int nt = 0; nt < 4; nt++) {
#pragma unroll
            for (int c = 0; c < 4; c++) {
                float s = sc[nt][c];
                float mm = (c < 2) ? m_lo : m_hi;
                float pv = (s > -1e29f) ? __expf(s - mm) : 0.f;
                sc[nt][c] = pv;
                if (c < 2) ps_lo += pv; else ps_hi += pv;
            }
        }
        l_lo = l_lo * al + ps_lo;
        l_hi = l_hi * ah + ps_hi;
#pragma unroll
        for (int nt = 0; nt < 16; nt++) {
            o[nt][0] *= al; o[nt][1] *= al; o[nt][2] *= ah; o[nt][3] *= ah;
        }

        // ---- PV over this warp's half of output HD ----
        const int src0 = (lane & ~3) | (tig >> 1);
        const int src1 = src0 + 2;
#pragma unroll
        for (int kk = 0; kk < 4; kk++) {
            float s0 = __shfl_sync(0xffffffffu, sc[kk][0], src0);
            float s1 = __shfl_sync(0xffffffffu, sc[kk][1], src0);
            float s2 = __shfl_sync(0xffffffffu, sc[kk][2], src0);
            float s3 = __shfl_sync(0xffffffffu, sc[kk][3], src0);
            float u0 = __shfl_sync(0xffffffffu, sc[kk][0], src1);
            float u1 = __shfl_sync(0xffffffffu, sc[kk][1], src1);
            float u2 = __shfl_sync(0xffffffffu, sc[kk][2], src1);
            float u3 = __shfl_sync(0xffffffffu, sc[kk][3], src1);
            unsigned a0 = f2tf((tig & 1) ? s1 : s0);
            unsigned a1 = f2tf((tig & 1) ? s3 : s2);
            unsigned a2 = f2tf((tig & 1) ? u1 : u0);
            unsigned a3 = f2tf((tig & 1) ? u3 : u2);
#pragma unroll
            for (int p = 0; p < 8; p++) {
                int pg = half * 8 + p;
                unsigned v0, v1, v2, v3;
                ldsm4(v0, v1, v2, v3, sv + (unsigned)(((pg * 16 + lrow) * AVP + kk * 8 + lcol) * 4));
                mma_tf32(o[2*p][0],   o[2*p][1],   o[2*p][2],   o[2*p][3],   a0, a1, a2, a3, v0, v1);
                mma_tf32(o[2*p+1][0], o[2*p+1][1], o[2*p+1][2], o[2*p+1][3], a0, a1, a2, a3, v2, v3);
            }
        }
    }

    l_lo += __shfl_xor_sync(0xffffffffu, l_lo, 1);
    l_lo += __shfl_xor_sync(0xffffffffu, l_lo, 2);
    l_hi += __shfl_xor_sync(0xffffffffu, l_hi, 1);
    l_hi += __shfl_xor_sync(0xffffffffu, l_hi, 2);
    float inv_lo = 1.0f / l_lo, inv_hi = 1.0f / l_hi;
#pragma unroll
    for (int nt = 0; nt < 16; nt++) {
        int col = h * HD + (half * 16 + nt) * 8 + 2 * tig;
        float2 lo = make_float2(__uint_as_float(f2tf(o[nt][0] * inv_lo)), __uint_as_float(f2tf(o[nt][1] * inv_lo)));
        float2 hi = make_float2(__uint_as_float(f2tf(o[nt][2] * inv_hi)), __uint_as_float(f2tf(o[nt][3] * inv_hi)));
        *(float2*)&out[(size_t)qi_lo * QDIM + col] = lo;
        *(float2*)&out[(size_t)qi_hi * QDIM + col] = hi;
    }
}

extern "C" void kernel_launch(void* const* d_in, const int* in_sizes, int n_in,
                              void* d_out, int out_size) {
    const float* x   = (const float*)d_in[0];
    const int*   pos = (const int*)  d_in[1];
    const float* Wq  = (const float*)d_in[2];
    const float* Wk  = (const float*)d_in[3];
    const float* Wv  = (const float*)d_in[4];
    const float* Wo  = (const float*)d_in[5];
    float* out = (float*)d_out;

    float *ao, *rx, *rwo;
    cudaGetSymbolAddress((void**)&ao,  g_ao);
    cudaGetSymbolAddress((void**)&rx,  g_x);
    cudaGetSymbolAddress((void**)&rwo, g_wo);

    int gsm = 6 * 128 * GKP * 4;   // 3 stages x (A+B)
    cudaFuncSetAttribute(gemm3<1>, cudaFuncAttributeMaxDynamicSharedMemorySize, gsm);
    cudaFuncSetAttribute(gemm3<0>, cudaFuncAttributeMaxDynamicSharedMemorySize, gsm);
    int asm_ = (SXOFF + 8 * 512) * 4;
    cudaFuncSetAttribute(attn_tc, cudaFuncAttributeMaxDynamicSharedMemorySize, asm_);

    round_copy<<<S_LEN*HID/1024, 256>>>(rx, x, S_LEN*HID/4);
    round_w3<<<9216, 256>>>(Wq, Wk, Wv);   // FIXED: 2359296 f4 total
    gemm3<1><<<dim3(4096/128, S_LEN/128), 128, gsm>>>(rx, nullptr, nullptr, 4096, HID);
    rope_kernel<<<S_LEN, 256>>>(pos);
    transpose_round_v<<<dim3(S_LEN/32, KVDIM/32), 256>>>();
    attn_tc<<<dim3(S_LEN/BQ, NH), 256, asm_>>>(ao);
    round_copy<<<HID*QDIM/1024, 256>>>(rwo, Wo, HID*QDIM/4);
    gemm3<0><<<dim3(HID/128, S_LEN/128), 128, gsm>>>(ao, rwo, out, HID, QDIM);
}